// round 13
// baseline (speedup 1.0000x reference)
#include <cuda_runtime.h>
#include <cuda_fp16.h>

// cumulative_hazard R10 (resubmit after infra failure): tensor-core RNN, k8 d!=c.
//  - 8 m16n8 tiles per warp (128 rows/warp, 128-thread blocks): 2x independent
//    mma->tanh chains per warp to cover MUFU/HMMA latency.
//  - y and tau staged in shared PRE-SPLATTED: u64 = (splat(y_row_g), splat(y_row_g+8));
//    inner loop = LDS.64 + 2x fma.rn.f16x2 (no PRMT/lane-extract), c-init off-chain.

typedef unsigned u32;
typedef unsigned long long u64;

#define NTHREADS 128
#define WARPS 4
#define TILES 8                       // m16n8 tiles per warp
#define ROWS_PER_WARP  (TILES * 16)   // 128
#define ROWS_PER_BLOCK (WARPS * ROWS_PER_WARP)  // 512

__device__ __forceinline__ u32 h2u(__half lo, __half hi) {
    __half2 v = __halves2half2(lo, hi);
    return *reinterpret_cast<u32*>(&v);
}
__device__ __forceinline__ u32 splat_u(float x) {
    __half h = __float2half(x);
    __half2 v = __halves2half2(h, h);
    return *reinterpret_cast<u32*>(&v);
}
__device__ __forceinline__ u32 hfma2u(u32 a, u32 b, u32 c) {
    u32 d; asm("fma.rn.f16x2 %0, %1, %2, %3;" : "=r"(d) : "r"(a), "r"(b), "r"(c));
    return d;
}
__device__ __forceinline__ u32 tanh_u(u32 v) {
    asm("tanh.approx.f16x2 %0, %0;" : "+r"(v));
    return v;
}
// mma m16n8k8 f16, separate D and C
__device__ __forceinline__ void mma1688_dc(u32& d0, u32& d1,
                                           u32 a0, u32 a1, u32 b0,
                                           u32 c0, u32 c1) {
    asm("mma.sync.aligned.m16n8k8.row.col.f16.f16.f16.f16 "
        "{%0,%1}, {%2,%3}, {%4}, {%5,%6};"
        : "=r"(d0), "=r"(d1)
        : "r"(a0), "r"(a1), "r"(b0), "r"(c0), "r"(c1));
}

__device__ __forceinline__ float softplus_out(float x) {
    float ax = fabsf(x);
    float l = log1pf(__expf(-ax));
    return x > 0.0f ? x + l : l;
}
__device__ __forceinline__ float sp_precise(float x) {
    float ax = fabsf(x);
    float l = log1pf(expf(-ax));
    return x > 0.0f ? x + l : l;
}

__global__ __launch_bounds__(NTHREADS)
void hazard_kernel(const float* __restrict__ Y,     // [N,16]
                   const float* __restrict__ tau,   // [N,1]
                   const float* __restrict__ f1W,   // [8,9]
                   const float* __restrict__ f1b,   // [8]
                   const float* __restrict__ ftW,   // [8,1]
                   const float* __restrict__ ftb,   // [8]
                   const float* __restrict__ f20W,  // [8,8]
                   const float* __restrict__ f20b,  // [8]
                   const float* __restrict__ f21W,  // [8,8]
                   const float* __restrict__ f21b,  // [8]
                   const float* __restrict__ f22W,  // [1,8]
                   const float* __restrict__ f22b,  // [1]
                   float* __restrict__ out,         // [N]
                   int N)
{
    __shared__ __half sW1[72], sB1[8];
    __shared__ __half sW20[64], sB20[8], sTW[8];
    __shared__ __half sW21[64], sB21[8];
    __shared__ float  sW22f[8];
    __shared__ float  sB22f;
    // pre-splatted: sY2[warp][tile][g][j] = { splat(y[row g]), splat(y[row g+8]) }
    __shared__ u32 sY2[WARPS * TILES * 8 * 11 * 2];
    __shared__ u32 sT2[WARPS * TILES * 8 * 2];

    const int t = threadIdx.x;
    // ---- weight preprocessing (softplus folded; f16) — strided over 128 thr ----
    for (int idx = t; idx < 241; idx += NTHREADS) {
        if (idx < 72)        { sW1[idx] = __float2half(f1W[idx]); }
        else if (idx < 80)   { int i = idx - 72;  sB1[i]  = __float2half(f1b[i]); }
        else if (idx < 144)  { int i = idx - 80;  sW20[i] = __float2half(f20W[i]); }
        else if (idx < 152)  { int i = idx - 144; sB20[i] = __float2half(f20b[i] + sp_precise(ftb[i])); }
        else if (idx < 160)  { int i = idx - 152; sTW[i]  = __float2half(sp_precise(ftW[i])); }
        else if (idx < 224)  { int i = idx - 160; sW21[i] = __float2half(sp_precise(f21W[i])); }
        else if (idx < 232)  { int i = idx - 224; sB21[i] = __float2half(sp_precise(f21b[i])); }
        else if (idx < 240)  { int i = idx - 232; sW22f[i] = sp_precise(f22W[i]); }
        else                 { sB22f = sp_precise(f22b[0]); }
    }
    __syncthreads();

    const int lane = t & 31;
    const int warp = t >> 5;
    const int g  = lane >> 2;   // 0..7
    const int tq = lane & 3;    // 0..3

    const long long base = (long long)blockIdx.x * ROWS_PER_BLOCK;

    // ---- stage y (log-gaps) & tau, pre-splatted. thread stages rows 4*lane..4*lane+3
    // of its own warp's 128-row block (writer warp == owner warp). ----
    {
        const int tile = lane >> 2;          // rows 4*lane.. all in this tile
        const int hs   = (lane >> 1) & 1;    // bit3 of local row (constant for 4 rows)
        u32* yW = sY2 + (warp * TILES) * 8 * 11 * 2;
        u32* tW = sT2 + (warp * TILES) * 8 * 2;

#pragma unroll 1
        for (int p = 0; p < 2; p++) {        // row pairs (g0, g0+1)
            const int g0 = (4 * lane & 7) + 2 * p;
            long long r0 = base + (long long)warp * ROWS_PER_WARP + 4 * lane + 2 * p;
            if (r0 > (long long)N - 2) r0 = (long long)N - 2;

            const float4* yp = (const float4*)(Y + r0 * 16);
            float4 q0 = yp[0], q1 = yp[1], q2 = yp[2], q3 = yp[3];
            float4 p0 = yp[4], p1 = yp[5], p2 = yp[6], p3 = yp[7];
            float ra[16] = { q0.x,q0.y,q0.z,q0.w, q1.x,q1.y,q1.z,q1.w,
                             q2.x,q2.y,q2.z,q2.w, q3.x,q3.y,q3.z,q3.w };
            float rb[16] = { p0.x,p0.y,p0.z,p0.w, p1.x,p1.y,p1.z,p1.w,
                             p2.x,p2.y,p2.z,p2.w, p3.x,p3.y,p3.z,p3.w };

#pragma unroll
            for (int j = 0; j < 11; j++) {
                float d0 = __logf(ra[4 + j] - ra[3 + j] + 0.1f);
                float d1 = __logf(rb[4 + j] - rb[3 + j] + 0.1f);
                yW[((tile * 8 + g0)     * 11 + j) * 2 + hs] = splat_u(d0);
                yW[((tile * 8 + g0 + 1) * 11 + j) * 2 + hs] = splat_u(d1);
            }
            float2 tv = *(const float2*)(tau + r0);
            tW[(tile * 8 + g0)     * 2 + hs] = splat_u(tv.x);
            tW[(tile * 8 + g0 + 1) * 2 + hs] = splat_u(tv.y);
        }
    }
    __syncwarp();

    // ---- per-thread fragment weights ----
    const u32 w1b0 = h2u(sW1[g * 9 + 2 * tq], sW1[g * 9 + 2 * tq + 1]);  // B: W1[n=g][k=2tq..]
    const u32 w8p  = h2u(sW1[(2 * tq) * 9 + 8], sW1[(2 * tq + 1) * 9 + 8]);
    const u32 bc1  = h2u(sB1[2 * tq], sB1[2 * tq + 1]);
    const u32 w20b = h2u(sW20[g * 8 + 2 * tq], sW20[g * 8 + 2 * tq + 1]);
    const u32 b20p = h2u(sB20[2 * tq], sB20[2 * tq + 1]);
    const u32 tWp  = h2u(sTW[2 * tq], sTW[2 * tq + 1]);
    const u32 w21b = h2u(sW21[g * 8 + 2 * tq], sW21[g * 8 + 2 * tq + 1]);
    const u32 b21p = h2u(sB21[2 * tq], sB21[2 * tq + 1]);
    const float w22a = sW22f[2 * tq], w22c = sW22f[2 * tq + 1];
    const float b22  = sB22f;

    const u32* yW = sY2 + (warp * TILES) * 8 * 11 * 2;
    const u32* tW = sT2 + (warp * TILES) * 8 * 2;

    // ---- RNN: 8 independent fragment chains, 11 steps ----
    u32 f0[TILES], f1r[TILES];

    // step 0: flow == 0 -> f = tanh(splat(y)*w8 + b)
#pragma unroll
    for (int tile = 0; tile < TILES; tile++) {
        const u32* ys = &yW[((tile * 8 + g) * 11) * 2];
        f0[tile]  = tanh_u(hfma2u(ys[0], w8p, bc1));
        f1r[tile] = tanh_u(hfma2u(ys[1], w8p, bc1));
    }

#pragma unroll
    for (int j = 1; j < 11; j++) {
#pragma unroll
        for (int tile = 0; tile < TILES; tile++) {
            const u32* ys = &yW[((tile * 8 + g) * 11 + j) * 2];
            u32 c0 = hfma2u(ys[0], w8p, bc1);    // off-chain C init
            u32 c1 = hfma2u(ys[1], w8p, bc1);
            u32 d0, d1;
            mma1688_dc(d0, d1, f0[tile], f1r[tile], w1b0, c0, c1);
            f0[tile]  = tanh_u(d0);
            f1r[tile] = tanh_u(d1);
        }
    }

    // ---- f2 layer 0: tanh(flow @ W20^T + b20' + tau*sp(Wtau)) ----
#pragma unroll
    for (int tile = 0; tile < TILES; tile++) {
        const u32* ts = &tW[(tile * 8 + g) * 2];
        u32 c0 = hfma2u(ts[0], tWp, b20p);
        u32 c1 = hfma2u(ts[1], tWp, b20p);
        u32 d0, d1;
        mma1688_dc(d0, d1, f0[tile], f1r[tile], w20b, c0, c1);
        f0[tile]  = tanh_u(d0);
        f1r[tile] = tanh_u(d1);
    }

    // ---- f2 layer 1: tanh(g @ sp(W21)^T + sp(b21)) ----
#pragma unroll
    for (int tile = 0; tile < TILES; tile++) {
        u32 d0, d1;
        mma1688_dc(d0, d1, f0[tile], f1r[tile], w21b, b21p, b21p);
        f0[tile]  = tanh_u(d0);
        f1r[tile] = tanh_u(d1);
    }

    // ---- output layer: f32 dot (quad-distributed) + shfl reduce ----
#pragma unroll
    for (int tile = 0; tile < TILES; tile++) {
        float2 fa = __half22float2(*reinterpret_cast<__half2*>(&f0[tile]));
        float2 fb = __half22float2(*reinterpret_cast<__half2*>(&f1r[tile]));
        float pl = fa.x * w22a + fa.y * w22c;
        float ph = fb.x * w22a + fb.y * w22c;
        pl += __shfl_xor_sync(0xFFFFFFFFu, pl, 1);
        pl += __shfl_xor_sync(0xFFFFFFFFu, pl, 2);
        ph += __shfl_xor_sync(0xFFFFFFFFu, ph, 1);
        ph += __shfl_xor_sync(0xFFFFFFFFu, ph, 2);
        if (tq == 0) {
            long long rlo = base + warp * ROWS_PER_WARP + tile * 16 + g;
            long long rhi = rlo + 8;
            if (rlo < N) out[rlo] = softplus_out(pl + b22);
            if (rhi < N) out[rhi] = softplus_out(ph + b22);
        }
    }
}

extern "C" void kernel_launch(void* const* d_in, const int* in_sizes, int n_in,
                              void* d_out, int out_size)
{
    const float* Y    = (const float*)d_in[0];
    const float* tau  = (const float*)d_in[1];
    const float* f1W  = (const float*)d_in[2];
    const float* f1b  = (const float*)d_in[3];
    const float* ftW  = (const float*)d_in[4];
    const float* ftb  = (const float*)d_in[5];
    const float* f20W = (const float*)d_in[6];
    const float* f20b = (const float*)d_in[7];
    const float* f21W = (const float*)d_in[8];
    const float* f21b = (const float*)d_in[9];
    const float* f22W = (const float*)d_in[10];
    const float* f22b = (const float*)d_in[11];
    float* out = (float*)d_out;

    int N = out_size;
    int blocks = (N + ROWS_PER_BLOCK - 1) / ROWS_PER_BLOCK;
    hazard_kernel<<<blocks, NTHREADS>>>(Y, tau, f1W, f1b, ftW, ftb,
                                        f20W, f20b, f21W, f21b, f22W, f22b,
                                        out, N);
}

// round 15
// speedup vs baseline: 1.1454x; 1.1454x over previous
#include <cuda_runtime.h>
#include <cuda_fp16.h>

// cumulative_hazard R13 (resubmit after infra failure): tensor-core RNN, k8 d!=c,
// instruction-diet pass.
//  - y staged [warp][tile][g][j-padded-to-12] as half2(row g, row g+8):
//    RNN reads it with LDS.128 (4 steps per load) -> 12 vector LDS instead of 44 scalar.
//  - ln2 folded into W1 column 8: y = log2f(gap+0.1), no FMUL per log.
//  - 256-thread blocks, 4 m16n8 tiles/warp, c-init off the mma critical chain.

typedef unsigned u32;

#define NTHREADS 256
#define WARPS 8
#define TILES 4
#define JPAD 12
#define ROWS_PER_BLOCK 512   // 8 warps x 64 rows

__device__ __forceinline__ __half2 u2h(u32 v) { return *reinterpret_cast<__half2*>(&v); }
__device__ __forceinline__ u32 h2u2(__half2 v) { return *reinterpret_cast<u32*>(&v); }
__device__ __forceinline__ u32 h2u(__half lo, __half hi) {
    __half2 v = __halves2half2(lo, hi);
    return *reinterpret_cast<u32*>(&v);
}
__device__ __forceinline__ u32 tanh_u(u32 v) {
    asm("tanh.approx.f16x2 %0, %0;" : "+r"(v));
    return v;
}
// mma m16n8k8 f16, separate D and C
__device__ __forceinline__ void mma1688_dc(u32& d0, u32& d1,
                                           u32 a0, u32 a1, u32 b0,
                                           u32 c0, u32 c1) {
    asm("mma.sync.aligned.m16n8k8.row.col.f16.f16.f16.f16 "
        "{%0,%1}, {%2,%3}, {%4}, {%5,%6};"
        : "=r"(d0), "=r"(d1)
        : "r"(a0), "r"(a1), "r"(b0), "r"(c0), "r"(c1));
}

__device__ __forceinline__ float softplus_out(float x) {
    float ax = fabsf(x);
    float l = log1pf(__expf(-ax));
    return x > 0.0f ? x + l : l;
}
__device__ __forceinline__ float sp_precise(float x) {
    float ax = fabsf(x);
    float l = log1pf(expf(-ax));
    return x > 0.0f ? x + l : l;
}

__global__ __launch_bounds__(NTHREADS)
void hazard_kernel(const float* __restrict__ Y,     // [N,16]
                   const float* __restrict__ tau,   // [N,1]
                   const float* __restrict__ f1W,   // [8,9]
                   const float* __restrict__ f1b,   // [8]
                   const float* __restrict__ ftW,   // [8,1]
                   const float* __restrict__ ftb,   // [8]
                   const float* __restrict__ f20W,  // [8,8]
                   const float* __restrict__ f20b,  // [8]
                   const float* __restrict__ f21W,  // [8,8]
                   const float* __restrict__ f21b,  // [8]
                   const float* __restrict__ f22W,  // [1,8]
                   const float* __restrict__ f22b,  // [1]
                   float* __restrict__ out,         // [N]
                   int N)
{
    __shared__ __half sW1[72], sB1[8];
    __shared__ __half sW20[64], sB20[8], sTW[8];
    __shared__ __half sW21[64], sB21[8];
    __shared__ float  sW22f[8];
    __shared__ float  sB22f;
    // y: [warp][tile][g][j(12)] as half2(row g, row g+8); 48B row pitch, 16B aligned
    __shared__ __align__(16) u32 sY[WARPS * TILES * 8 * JPAD];
    __shared__ u32 sTau[WARPS * TILES * 8];

    const int t = threadIdx.x;
    // ---- weight preprocessing (softplus folded; f16; ln2 folded into W1 col 8) ----
    if (t < 72)        { float s = (t % 9 == 8) ? 0.69314718056f : 1.0f;
                         sW1[t] = __float2half(f1W[t] * s); }
    else if (t < 80)   { int i = t - 72;  sB1[i]  = __float2half(f1b[i]); }
    else if (t < 144)  { int i = t - 80;  sW20[i] = __float2half(f20W[i]); }
    else if (t < 152)  { int i = t - 144; sB20[i] = __float2half(f20b[i] + sp_precise(ftb[i])); }
    else if (t < 160)  { int i = t - 152; sTW[i]  = __float2half(sp_precise(ftW[i])); }
    else if (t < 224)  { int i = t - 160; sW21[i] = __float2half(sp_precise(f21W[i])); }
    else if (t < 232)  { int i = t - 224; sB21[i] = __float2half(sp_precise(f21b[i])); }
    else if (t < 240)  { int i = t - 232; sW22f[i] = sp_precise(f22W[i]); }
    else if (t == 240) { sB22f = sp_precise(f22b[0]); }
    __syncthreads();

    const int lane = t & 31;
    const int warp = t >> 5;
    const int g  = lane >> 2;   // 0..7
    const int tq = lane & 3;    // 0..3

    const long long base = (long long)blockIdx.x * ROWS_PER_BLOCK;

    // ---- stage y (log2-gaps) & tau. thread stages local rows 2t, 2t+1
    // (writer warp == owner warp). ----
    {
        const int rp = 2 * t;
        long long r0 = base + rp;
        if (r0 > (long long)N - 2) r0 = (long long)N - 2;

        const float4* yp = (const float4*)(Y + r0 * 16);
        float4 q0 = yp[0], q1 = yp[1], q2 = yp[2], q3 = yp[3];
        float4 p0 = yp[4], p1 = yp[5], p2 = yp[6], p3 = yp[7];
        float ra[16] = { q0.x,q0.y,q0.z,q0.w, q1.x,q1.y,q1.z,q1.w,
                         q2.x,q2.y,q2.z,q2.w, q3.x,q3.y,q3.z,q3.w };
        float rb[16] = { p0.x,p0.y,p0.z,p0.w, p1.x,p1.y,p1.z,p1.w,
                         p2.x,p2.y,p2.z,p2.w, p3.x,p3.y,p3.z,p3.w };

        __half* yh = reinterpret_cast<__half*>(sY);
        __half* th = reinterpret_cast<__half*>(sTau);

        const int tile = (rp >> 4) & 3;
        const int hs   = (rp >> 3) & 1;
        const int g0   = rp & 7;          // even
#pragma unroll
        for (int j = 0; j < 11; j++) {
            float d0 = __log2f(ra[4 + j] - ra[3 + j] + 0.1f);   // ln2 folded into W1 col8
            float d1 = __log2f(rb[4 + j] - rb[3 + j] + 0.1f);
            int i0 = (((warp * TILES + tile) * 8 + g0)     * JPAD + j) * 2 + hs;
            int i1 = (((warp * TILES + tile) * 8 + g0 + 1) * JPAD + j) * 2 + hs;
            yh[i0] = __float2half(d0);
            yh[i1] = __float2half(d1);
        }
        float2 tv = *(const float2*)(tau + r0);
        th[((warp * TILES + tile) * 8 + g0)     * 2 + hs] = __float2half(tv.x);
        th[((warp * TILES + tile) * 8 + g0 + 1) * 2 + hs] = __float2half(tv.y);
    }
    __syncwarp();

    // ---- per-thread fragment weights ----
    const u32 w1b0 = h2u(sW1[g * 9 + 2 * tq], sW1[g * 9 + 2 * tq + 1]);   // B: W1[n=g][k=2tq..]
    const __half2 w8p = __halves2half2(sW1[(2 * tq) * 9 + 8],             // (ln2-scaled) y weights
                                       sW1[(2 * tq + 1) * 9 + 8]);
    const __half2 bc1 = __halves2half2(sB1[2 * tq], sB1[2 * tq + 1]);
    const u32 w20b  = h2u(sW20[g * 8 + 2 * tq], sW20[g * 8 + 2 * tq + 1]);
    const __half2 b20p = __halves2half2(sB20[2 * tq], sB20[2 * tq + 1]);
    const __half2 tWp  = __halves2half2(sTW[2 * tq], sTW[2 * tq + 1]);
    const u32 w21b  = h2u(sW21[g * 8 + 2 * tq], sW21[g * 8 + 2 * tq + 1]);
    const u32 b21p  = h2u(sB21[2 * tq], sB21[2 * tq + 1]);
    const float w22a = sW22f[2 * tq], w22c = sW22f[2 * tq + 1];
    const float b22  = sB22f;

    const u32* yW  = sY + (warp * TILES) * 8 * JPAD;
    const u32* tW2 = sTau + (warp * TILES) * 8;

    // ---- RNN: 4 fragment chains, 11 steps, y read 4 steps at a time (LDS.128) ----
    u32 f0[TILES], f1r[TILES];

#pragma unroll
    for (int jg = 0; jg < 3; jg++) {
        u32 yv[TILES][4];
#pragma unroll
        for (int tile = 0; tile < TILES; tile++) {
            uint4 v = *(const uint4*)&yW[(tile * 8 + g) * JPAD + jg * 4];
            yv[tile][0] = v.x; yv[tile][1] = v.y; yv[tile][2] = v.z; yv[tile][3] = v.w;
        }
#pragma unroll
        for (int jj = 0; jj < 4; jj++) {
            const int j = jg * 4 + jj;
            if (j == 0) {
                // step 0: flow == 0 -> f = tanh(splat(y)*w8 + b)
#pragma unroll
                for (int tile = 0; tile < TILES; tile++) {
                    __half2 yh2 = u2h(yv[tile][jj]);
                    f0[tile]  = tanh_u(h2u2(__hfma2(__low2half2(yh2),  w8p, bc1)));
                    f1r[tile] = tanh_u(h2u2(__hfma2(__high2half2(yh2), w8p, bc1)));
                }
            } else if (j < 11) {
#pragma unroll
                for (int tile = 0; tile < TILES; tile++) {
                    __half2 yh2 = u2h(yv[tile][jj]);
                    u32 c0 = h2u2(__hfma2(__low2half2(yh2),  w8p, bc1));  // off-chain C init
                    u32 c1 = h2u2(__hfma2(__high2half2(yh2), w8p, bc1));
                    u32 d0, d1;
                    mma1688_dc(d0, d1, f0[tile], f1r[tile], w1b0, c0, c1);
                    f0[tile]  = tanh_u(d0);
                    f1r[tile] = tanh_u(d1);
                }
            }
        }
    }

    // ---- f2 layer 0: tanh(flow @ W20^T + b20' + tau*sp(Wtau)) ----
#pragma unroll
    for (int tile = 0; tile < TILES; tile++) {
        __half2 tp = u2h(tW2[tile * 8 + g]);
        u32 c0 = h2u2(__hfma2(__low2half2(tp),  tWp, b20p));
        u32 c1 = h2u2(__hfma2(__high2half2(tp), tWp, b20p));
        u32 d0, d1;
        mma1688_dc(d0, d1, f0[tile], f1r[tile], w20b, c0, c1);
        f0[tile]  = tanh_u(d0);
        f1r[tile] = tanh_u(d1);
    }

    // ---- f2 layer 1: tanh(g @ sp(W21)^T + sp(b21)) ----
#pragma unroll
    for (int tile = 0; tile < TILES; tile++) {
        u32 d0, d1;
        mma1688_dc(d0, d1, f0[tile], f1r[tile], w21b, b21p, b21p);
        f0[tile]  = tanh_u(d0);
        f1r[tile] = tanh_u(d1);
    }

    // ---- output layer: f32 dot (quad-distributed) + shfl reduce ----
#pragma unroll
    for (int tile = 0; tile < TILES; tile++) {
        float2 fa = __half22float2(u2h(f0[tile]));   // row g:   cols 2tq,2tq+1
        float2 fb = __half22float2(u2h(f1r[tile]));  // row g+8
        float pl = fa.x * w22a + fa.y * w22c;
        float ph = fb.x * w22a + fb.y * w22c;
        pl += __shfl_xor_sync(0xFFFFFFFFu, pl, 1);
        pl += __shfl_xor_sync(0xFFFFFFFFu, pl, 2);
        ph += __shfl_xor_sync(0xFFFFFFFFu, ph, 1);
        ph += __shfl_xor_sync(0xFFFFFFFFu, ph, 2);
        if (tq == 0) {
            long long rlo = base + warp * 64 + tile * 16 + g;
            long long rhi = rlo + 8;
            if (rlo < N) out[rlo] = softplus_out(pl + b22);
            if (rhi < N) out[rhi] = softplus_out(ph + b22);
        }
    }
}

extern "C" void kernel_launch(void* const* d_in, const int* in_sizes, int n_in,
                              void* d_out, int out_size)
{
    const float* Y    = (const float*)d_in[0];
    const float* tau  = (const float*)d_in[1];
    const float* f1W  = (const float*)d_in[2];
    const float* f1b  = (const float*)d_in[3];
    const float* ftW  = (const float*)d_in[4];
    const float* ftb  = (const float*)d_in[5];
    const float* f20W = (const float*)d_in[6];
    const float* f20b = (const float*)d_in[7];
    const float* f21W = (const float*)d_in[8];
    const float* f21b = (const float*)d_in[9];
    const float* f22W = (const float*)d_in[10];
    const float* f22b = (const float*)d_in[11];
    float* out = (float*)d_out;

    int N = out_size;
    int blocks = (N + ROWS_PER_BLOCK - 1) / ROWS_PER_BLOCK;
    hazard_kernel<<<blocks, NTHREADS>>>(Y, tau, f1W, f1b, ftW, ftb,
                                        f20W, f20b, f21W, f21b, f22W, f22b,
                                        out, N);
}